// round 7
// baseline (speedup 1.0000x reference)
#include <cuda_runtime.h>

// ICLoss: negative soft-rank information coefficient.
//   r_i = sum_j sigmoid(x_i - x_j) + 1
// Using u = exp(x):  sigmoid(x_i - x_j) = u_i / (u_i + u_j)
//   => r_i = u_i * sum_j 1/(u_i + u_j) + 1
// Inner loop pairs two reciprocals per MUFU.RCP:
//   1/t1 + 1/t2 = (t1 + t2) * rcp(t1 * t2)
// and computes (t1, t2) with one packed add.rn.f32x2.

#define NN 8192
#define JSPLIT 16
#define CHUNK 512            // NN / JSPLIT
#define ROWS 256             // rows per block
#define ROWBLKS 32           // NN / ROWS

// Scratch: partial rank sums (no device allocation allowed -> __device__ global).
__device__ float g_part[2][JSPLIT][NN];

__global__ void __launch_bounds__(256) rank_kernel(const float* __restrict__ pred,
                                                   const float* __restrict__ targ) {
    __shared__ unsigned long long su[CHUNK / 2];   // packed (e^x_j, e^x_{j+1})

    const int b   = blockIdx.x;
    const int js  = b & (JSPLIT - 1);        // which 512-column chunk
    const int rb  = (b >> 4) & (ROWBLKS - 1);// which 256-row block
    const int m   = b >> 9;                  // 0 = predictions, 1 = targets
    const int tid = threadIdx.x;

    const float* __restrict__ x = m ? targ : pred;

    // Load this block's j-chunk, exponentiate, pack into shared as f32x2.
    {
        float2 xj = reinterpret_cast<const float2*>(x + js * CHUNK)[tid];
        unsigned int a = __float_as_uint(__expf(xj.x));
        unsigned int c = __float_as_uint(__expf(xj.y));
        su[tid] = ((unsigned long long)c << 32) | (unsigned long long)a;
    }

    const int i = rb * ROWS + tid;
    const float ui = __expf(x[i]);
    __syncthreads();

    const unsigned int uib = __float_as_uint(ui);
    const unsigned long long ui2 = ((unsigned long long)uib << 32) | (unsigned long long)uib;

    // acc = sum over chunk of 1/(ui + uj)
    float acc = 0.0f;
#pragma unroll 8
    for (int k = 0; k < CHUNK / 2; ++k) {
        unsigned long long uj = su[k];
        unsigned long long t64;
        asm("add.rn.f32x2 %0, %1, %2;" : "=l"(t64) : "l"(ui2), "l"(uj));
        unsigned int lo, hi;
        asm("mov.b64 {%0, %1}, %2;" : "=r"(lo), "=r"(hi) : "l"(t64));
        float t1 = __uint_as_float(lo);
        float t2 = __uint_as_float(hi);
        float p = t1 * t2;          // t1*t2
        float s = t1 + t2;          // t1+t2
        float r;
        asm("rcp.approx.f32 %0, %1;" : "=f"(r) : "f"(p));
        acc = __fmaf_rn(s, r, acc); // += (t1+t2)/(t1*t2) = 1/t1 + 1/t2
    }

    g_part[m][js][i] = ui * acc;    // partial of sum_j sigmoid(x_i - x_j)
}

// Single-block finalize: assemble ranks, compute Pearson corr of ranks in fp64
// with a fixed deterministic reduction order, write -ic.
__global__ void __launch_bounds__(1024) finalize_kernel(float* __restrict__ out) {
    __shared__ double red[5][32];
    const int tid  = threadIdx.x;
    const int lane = tid & 31;
    const int w    = tid >> 5;

    double sp = 0.0, st = 0.0, spp = 0.0, stt = 0.0, spt = 0.0;

    for (int r = tid; r < NN; r += 1024) {
        float rp = 1.0f, rt = 1.0f;   // +1.0 from the reference rank definition
#pragma unroll
        for (int s = 0; s < JSPLIT; ++s) {
            rp += g_part[0][s][r];
            rt += g_part[1][s][r];
        }
        double dp = (double)rp, dt = (double)rt;
        sp  += dp;       st  += dt;
        spp += dp * dp;  stt += dt * dt;
        spt += dp * dt;
    }

    // warp reduction
#pragma unroll
    for (int o = 16; o > 0; o >>= 1) {
        sp  += __shfl_down_sync(0xffffffffu, sp,  o);
        st  += __shfl_down_sync(0xffffffffu, st,  o);
        spp += __shfl_down_sync(0xffffffffu, spp, o);
        stt += __shfl_down_sync(0xffffffffu, stt, o);
        spt += __shfl_down_sync(0xffffffffu, spt, o);
    }
    if (lane == 0) {
        red[0][w] = sp;  red[1][w] = st;
        red[2][w] = spp; red[3][w] = stt; red[4][w] = spt;
    }
    __syncthreads();

    if (w == 0) {
        sp  = red[0][lane];
        st  = red[1][lane];
        spp = red[2][lane];
        stt = red[3][lane];
        spt = red[4][lane];
#pragma unroll
        for (int o = 16; o > 0; o >>= 1) {
            sp  += __shfl_down_sync(0xffffffffu, sp,  o);
            st  += __shfl_down_sync(0xffffffffu, st,  o);
            spp += __shfl_down_sync(0xffffffffu, spp, o);
            stt += __shfl_down_sync(0xffffffffu, stt, o);
            spt += __shfl_down_sync(0xffffffffu, spt, o);
        }
        if (lane == 0) {
            const double n  = (double)NN;
            const double mp = sp / n;
            const double mt = st / n;
            double num = spt - n * mp * mt;          // sum(p_c * t_c)
            double dpp = spp - n * mp * mp;          // sum(p_c^2)
            double dtt = stt - n * mt * mt;          // sum(t_c^2)
            double ic  = num / (sqrt(dpp * dtt) + 1e-8);
            out[0] = (float)(-ic);
        }
    }
}

extern "C" void kernel_launch(void* const* d_in, const int* in_sizes, int n_in,
                              void* d_out, int out_size) {
    const float* pred = (const float*)d_in[0];
    const float* targ = (const float*)d_in[1];

    // 2 matrices * 32 row-blocks * 16 j-splits = 1024 blocks, all co-resident.
    rank_kernel<<<2 * ROWBLKS * JSPLIT, 256>>>(pred, targ);
    finalize_kernel<<<1, 1024>>>((float*)d_out);
}

// round 8
// speedup vs baseline: 1.0379x; 1.0379x over previous
#include <cuda_runtime.h>

// ICLoss: negative soft-rank information coefficient.
//   r_i = sum_j sigmoid(x_i - x_j) + 1
// Using u = exp(x):  sigmoid(x_i - x_j) = u_i / (u_i + u_j)
//   => r_i = u_i * sum_j 1/(u_i + u_j) + 1
// Inner loop pairs two reciprocals per MUFU.RCP:
//   1/t1 + 1/t2 = (t1 + t2) * rcp(t1 * t2)
// and computes (t1, t2) with one packed add.rn.f32x2.

#define NN 8192
#define JSPLIT 16
#define CHUNK 512            // NN / JSPLIT
#define ROWS 256             // rows per block
#define ROWBLKS 32           // NN / ROWS

// Scratch: partial rank sums (no device allocation allowed -> __device__ global).
__device__ float g_part[2][JSPLIT][NN];

__global__ void __launch_bounds__(256) rank_kernel(const float* __restrict__ pred,
                                                   const float* __restrict__ targ) {
    __shared__ unsigned long long su[CHUNK / 2];   // packed (e^x_j, e^x_{j+1})

    const int b   = blockIdx.x;
    const int js  = b & (JSPLIT - 1);        // which 512-column chunk
    const int rb  = (b >> 4) & (ROWBLKS - 1);// which 256-row block
    const int m   = b >> 9;                  // 0 = predictions, 1 = targets
    const int tid = threadIdx.x;

    const float* __restrict__ x = m ? targ : pred;

    // Load this block's j-chunk, exponentiate, pack into shared as f32x2.
    {
        float2 xj = reinterpret_cast<const float2*>(x + js * CHUNK)[tid];
        unsigned int a = __float_as_uint(__expf(xj.x));
        unsigned int c = __float_as_uint(__expf(xj.y));
        su[tid] = ((unsigned long long)c << 32) | (unsigned long long)a;
    }

    const int i = rb * ROWS + tid;
    const float ui = __expf(x[i]);
    __syncthreads();

    const unsigned int uib = __float_as_uint(ui);
    const unsigned long long ui2 = ((unsigned long long)uib << 32) | (unsigned long long)uib;

    // acc = sum over chunk of 1/(ui + uj)
    float acc = 0.0f;
#pragma unroll 8
    for (int k = 0; k < CHUNK / 2; ++k) {
        unsigned long long uj = su[k];
        unsigned long long t64;
        asm("add.rn.f32x2 %0, %1, %2;" : "=l"(t64) : "l"(ui2), "l"(uj));
        unsigned int lo, hi;
        asm("mov.b64 {%0, %1}, %2;" : "=r"(lo), "=r"(hi) : "l"(t64));
        float t1 = __uint_as_float(lo);
        float t2 = __uint_as_float(hi);
        float p = t1 * t2;          // t1*t2
        float s = t1 + t2;          // t1+t2
        float r;
        asm("rcp.approx.f32 %0, %1;" : "=f"(r) : "f"(p));
        acc = __fmaf_rn(s, r, acc); // += (t1+t2)/(t1*t2) = 1/t1 + 1/t2
    }

    g_part[m][js][i] = ui * acc;    // partial of sum_j sigmoid(x_i - x_j)
}

// Single-block finalize: assemble ranks, compute Pearson corr of ranks in fp64
// with a fixed deterministic reduction order, write -ic.
__global__ void __launch_bounds__(1024) finalize_kernel(float* __restrict__ out) {
    __shared__ double red[5][32];
    const int tid  = threadIdx.x;
    const int lane = tid & 31;
    const int w    = tid >> 5;

    double sp = 0.0, st = 0.0, spp = 0.0, stt = 0.0, spt = 0.0;

    for (int r = tid; r < NN; r += 1024) {
        float rp = 1.0f, rt = 1.0f;   // +1.0 from the reference rank definition
#pragma unroll
        for (int s = 0; s < JSPLIT; ++s) {
            rp += g_part[0][s][r];
            rt += g_part[1][s][r];
        }
        double dp = (double)rp, dt = (double)rt;
        sp  += dp;       st  += dt;
        spp += dp * dp;  stt += dt * dt;
        spt += dp * dt;
    }

    // warp reduction
#pragma unroll
    for (int o = 16; o > 0; o >>= 1) {
        sp  += __shfl_down_sync(0xffffffffu, sp,  o);
        st  += __shfl_down_sync(0xffffffffu, st,  o);
        spp += __shfl_down_sync(0xffffffffu, spp, o);
        stt += __shfl_down_sync(0xffffffffu, stt, o);
        spt += __shfl_down_sync(0xffffffffu, spt, o);
    }
    if (lane == 0) {
        red[0][w] = sp;  red[1][w] = st;
        red[2][w] = spp; red[3][w] = stt; red[4][w] = spt;
    }
    __syncthreads();

    if (w == 0) {
        sp  = red[0][lane];
        st  = red[1][lane];
        spp = red[2][lane];
        stt = red[3][lane];
        spt = red[4][lane];
#pragma unroll
        for (int o = 16; o > 0; o >>= 1) {
            sp  += __shfl_down_sync(0xffffffffu, sp,  o);
            st  += __shfl_down_sync(0xffffffffu, st,  o);
            spp += __shfl_down_sync(0xffffffffu, spp, o);
            stt += __shfl_down_sync(0xffffffffu, stt, o);
            spt += __shfl_down_sync(0xffffffffu, spt, o);
        }
        if (lane == 0) {
            const double n  = (double)NN;
            const double mp = sp / n;
            const double mt = st / n;
            double num = spt - n * mp * mt;          // sum(p_c * t_c)
            double dpp = spp - n * mp * mp;          // sum(p_c^2)
            double dtt = stt - n * mt * mt;          // sum(t_c^2)
            double ic  = num / (sqrt(dpp * dtt) + 1e-8);
            out[0] = (float)(-ic);
        }
    }
}

extern "C" void kernel_launch(void* const* d_in, const int* in_sizes, int n_in,
                              void* d_out, int out_size) {
    const float* pred = (const float*)d_in[0];
    const float* targ = (const float*)d_in[1];

    // 2 matrices * 32 row-blocks * 16 j-splits = 1024 blocks, all co-resident.
    rank_kernel<<<2 * ROWBLKS * JSPLIT, 256>>>(pred, targ);
    finalize_kernel<<<1, 1024>>>((float*)d_out);
}

// round 9
// speedup vs baseline: 1.3311x; 1.2826x over previous
#include <cuda_runtime.h>

// ICLoss: negative soft-rank information coefficient.
//   r_i = sum_j sigmoid(x_i - x_j) + 1
// Using u = exp(x):  sigmoid(x_i - x_j) = u_i / (u_i + u_j)
//   => r_i = u_i * sum_j 1/(u_i + u_j) + 1
// Inner loop pairs two reciprocals per MUFU.RCP:
//   1/t1 + 1/t2 = (t1 + t2) * rcp(t1 * t2)
// and computes (t1, t2) with one packed add.rn.f32x2.
//
// Epilogue is split into a 32-block fp64 stats pass + 1-thread combine so the
// O(N) work no longer serializes on a single SM (was 37us of 55.8us).

#define NN 8192
#define JSPLIT 16
#define CHUNK 512            // NN / JSPLIT
#define ROWS 256             // rows per block
#define ROWBLKS 32           // NN / ROWS

#define SBLOCKS 32           // stats blocks
#define SROWS   256          // rows per stats block (NN / SBLOCKS)

// Scratch (no device allocation allowed -> __device__ globals).
__device__ float  g_part[2][JSPLIT][NN];
__device__ double g_stats[SBLOCKS][5];

__global__ void __launch_bounds__(256) rank_kernel(const float* __restrict__ pred,
                                                   const float* __restrict__ targ) {
    __shared__ unsigned long long su[CHUNK / 2];   // packed (e^x_j, e^x_{j+1})

    const int b   = blockIdx.x;
    const int js  = b & (JSPLIT - 1);        // which 512-column chunk
    const int rb  = (b >> 4) & (ROWBLKS - 1);// which 256-row block
    const int m   = b >> 9;                  // 0 = predictions, 1 = targets
    const int tid = threadIdx.x;

    const float* __restrict__ x = m ? targ : pred;

    // Load this block's j-chunk, exponentiate, pack into shared as f32x2.
    {
        float2 xj = reinterpret_cast<const float2*>(x + js * CHUNK)[tid];
        unsigned int a = __float_as_uint(__expf(xj.x));
        unsigned int c = __float_as_uint(__expf(xj.y));
        su[tid] = ((unsigned long long)c << 32) | (unsigned long long)a;
    }

    const int i = rb * ROWS + tid;
    const float ui = __expf(x[i]);
    __syncthreads();

    const unsigned int uib = __float_as_uint(ui);
    const unsigned long long ui2 = ((unsigned long long)uib << 32) | (unsigned long long)uib;

    // acc = sum over chunk of 1/(ui + uj)
    float acc = 0.0f;
#pragma unroll 8
    for (int k = 0; k < CHUNK / 2; ++k) {
        unsigned long long uj = su[k];
        unsigned long long t64;
        asm("add.rn.f32x2 %0, %1, %2;" : "=l"(t64) : "l"(ui2), "l"(uj));
        unsigned int lo, hi;
        asm("mov.b64 {%0, %1}, %2;" : "=r"(lo), "=r"(hi) : "l"(t64));
        float t1 = __uint_as_float(lo);
        float t2 = __uint_as_float(hi);
        float p = t1 * t2;          // t1*t2
        float s = t1 + t2;          // t1+t2
        float r;
        asm("rcp.approx.f32 %0, %1;" : "=f"(r) : "f"(p));
        acc = __fmaf_rn(s, r, acc); // += (t1+t2)/(t1*t2) = 1/t1 + 1/t2
    }

    g_part[m][js][i] = ui * acc;    // partial of sum_j sigmoid(x_i - x_j)
}

// Stage 2: 32 blocks x 256 threads, one row per thread. Assemble ranks from the
// 16 j-split partials, accumulate 5 fp64 moments, block-reduce in a fixed
// order, write per-block partials. Deterministic (no atomics).
__global__ void __launch_bounds__(256) stats_kernel() {
    __shared__ double red[5][8];
    const int tid  = threadIdx.x;
    const int lane = tid & 31;
    const int w    = tid >> 5;
    const int r    = blockIdx.x * SROWS + tid;

    float rp = 1.0f, rt = 1.0f;   // +1.0 from the reference rank definition
#pragma unroll
    for (int s = 0; s < JSPLIT; ++s) {
        rp += g_part[0][s][r];
        rt += g_part[1][s][r];
    }
    double dp = (double)rp, dt = (double)rt;
    double sp  = dp,      st  = dt;
    double spp = dp * dp, stt = dt * dt, spt = dp * dt;

    // warp reduction (fixed order)
#pragma unroll
    for (int o = 16; o > 0; o >>= 1) {
        sp  += __shfl_down_sync(0xffffffffu, sp,  o);
        st  += __shfl_down_sync(0xffffffffu, st,  o);
        spp += __shfl_down_sync(0xffffffffu, spp, o);
        stt += __shfl_down_sync(0xffffffffu, stt, o);
        spt += __shfl_down_sync(0xffffffffu, spt, o);
    }
    if (lane == 0) {
        red[0][w] = sp;  red[1][w] = st;
        red[2][w] = spp; red[3][w] = stt; red[4][w] = spt;
    }
    __syncthreads();

    if (tid == 0) {
        double a0 = 0, a1 = 0, a2 = 0, a3 = 0, a4 = 0;
#pragma unroll
        for (int k = 0; k < 8; ++k) {
            a0 += red[0][k]; a1 += red[1][k]; a2 += red[2][k];
            a3 += red[3][k]; a4 += red[4][k];
        }
        g_stats[blockIdx.x][0] = a0;
        g_stats[blockIdx.x][1] = a1;
        g_stats[blockIdx.x][2] = a2;
        g_stats[blockIdx.x][3] = a3;
        g_stats[blockIdx.x][4] = a4;
    }
}

// Stage 3: single thread combines the 32 block partials in fixed order.
__global__ void combine_kernel(float* __restrict__ out) {
    double sp = 0, st = 0, spp = 0, stt = 0, spt = 0;
#pragma unroll
    for (int k = 0; k < SBLOCKS; ++k) {
        sp  += g_stats[k][0];
        st  += g_stats[k][1];
        spp += g_stats[k][2];
        stt += g_stats[k][3];
        spt += g_stats[k][4];
    }
    const double n  = (double)NN;
    const double mp = sp / n;
    const double mt = st / n;
    double num = spt - n * mp * mt;          // sum(p_c * t_c)
    double dpp = spp - n * mp * mp;          // sum(p_c^2)
    double dtt = stt - n * mt * mt;          // sum(t_c^2)
    double ic  = num / (sqrt(dpp * dtt) + 1e-8);
    out[0] = (float)(-ic);
}

extern "C" void kernel_launch(void* const* d_in, const int* in_sizes, int n_in,
                              void* d_out, int out_size) {
    const float* pred = (const float*)d_in[0];
    const float* targ = (const float*)d_in[1];

    // 2 matrices * 32 row-blocks * 16 j-splits = 1024 blocks, all co-resident.
    rank_kernel<<<2 * ROWBLKS * JSPLIT, 256>>>(pred, targ);
    stats_kernel<<<SBLOCKS, SROWS>>>();
    combine_kernel<<<1, 1>>>((float*)d_out);
}

// round 10
// speedup vs baseline: 1.7261x; 1.2968x over previous
#include <cuda_runtime.h>

// ICLoss: negative soft-rank information coefficient.
//   r_i = sum_j sigmoid(x_i - x_j) + 1
// Using u = exp(x):  sigmoid(x_i - x_j) = u_i / (u_i + u_j)
//   => r_i = u_i * sum_j 1/(u_i + u_j) + 1
//
// Round-10 inner loop: 4-way reciprocal grouping with per-group precomputed
// symmetric polynomials. For a group {j1..j4} precompute (in SMEM, once per
// block): s12 = u1+u2, p12 = u1*u2, s34 = u3+u4, p34 = u3*u4. Then with
// t_k = ui + u_jk:
//   q1 = (ui+u1)(ui+u2) = fma(s12, ui, p12) + ui^2      (same for q2)
//   d1 = t1 + t2 = s12 + 2*ui                            (same for d2)
//   1/t1 + 1/t2 + 1/t3 + 1/t4 = (d1*q2 + d2*q1) * rcp(q1*q2)
// => 1 LDS.128 + 9 flops + 1 MUFU per FOUR pairs (was ~13 instrs per 2 pairs).

#define NN 8192
#define JSPLIT 16
#define CHUNK 512            // NN / JSPLIT
#define GROUPS (CHUNK / 4)   // 128 groups of 4 j's
#define ROWS 256             // rows per block
#define ROWBLKS 32           // NN / ROWS

#define SBLOCKS 32           // stats blocks
#define SROWS   256          // rows per stats block (NN / SBLOCKS)

// Scratch (no device allocation allowed -> __device__ globals).
// Transposed layout: row-major over jsplit so stats can read float4s.
__device__ float  g_part[2][NN][JSPLIT];
__device__ double g_stats[SBLOCKS][5];

__global__ void __launch_bounds__(256) rank_kernel(const float* __restrict__ pred,
                                                   const float* __restrict__ targ) {
    __shared__ float4 sg[GROUPS];   // (s12, p12, s34, p34) per group of 4 j's

    const int b   = blockIdx.x;
    const int js  = b & (JSPLIT - 1);        // which 512-column chunk
    const int rb  = (b >> 4) & (ROWBLKS - 1);// which 256-row block
    const int m   = b >> 9;                  // 0 = predictions, 1 = targets
    const int tid = threadIdx.x;

    const float* __restrict__ x = m ? targ : pred;

    // Fill this block's j-chunk group data (threads 0..127).
    if (tid < GROUPS) {
        float4 xx = reinterpret_cast<const float4*>(x + js * CHUNK)[tid];
        float u1 = __expf(xx.x), u2 = __expf(xx.y);
        float u3 = __expf(xx.z), u4 = __expf(xx.w);
        sg[tid] = make_float4(u1 + u2, u1 * u2, u3 + u4, u3 * u4);
    }

    const int   i   = rb * ROWS + tid;
    const float ui  = __expf(x[i]);
    const float ui2 = ui * ui;
    const float tu  = ui + ui;
    __syncthreads();

    // acc = sum over chunk of 1/(ui + uj)
    float acc = 0.0f;
#pragma unroll 8
    for (int k = 0; k < GROUPS; ++k) {
        float4 g = sg[k];
        float q1 = __fmaf_rn(g.x, ui, g.y) + ui2;   // (ui+u1)(ui+u2)
        float q2 = __fmaf_rn(g.z, ui, g.w) + ui2;   // (ui+u3)(ui+u4)
        float d1 = g.x + tu;                        // t1 + t2
        float d2 = g.z + tu;                        // t3 + t4
        float p  = q1 * q2;
        float n  = __fmaf_rn(d2, q1, d1 * q2);
        float r;
        asm("rcp.approx.f32 %0, %1;" : "=f"(r) : "f"(p));
        acc = __fmaf_rn(n, r, acc);                 // += 1/t1+1/t2+1/t3+1/t4
    }

    g_part[m][i][js] = ui * acc;    // partial of sum_j sigmoid(x_i - x_j)
}

// Stage 2: 32 blocks x 256 threads, one row per thread. Assemble ranks from the
// 16 j-split partials (4 coalesced float4 loads per matrix), accumulate 5 fp64
// moments, block-reduce in a fixed order, write per-block partials.
__global__ void __launch_bounds__(256) stats_kernel() {
    __shared__ double red[5][8];
    const int tid  = threadIdx.x;
    const int lane = tid & 31;
    const int w    = tid >> 5;
    const int r    = blockIdx.x * SROWS + tid;

    float rp = 1.0f, rt = 1.0f;   // +1.0 from the reference rank definition
    const float4* pp = reinterpret_cast<const float4*>(g_part[0][r]);
    const float4* tp = reinterpret_cast<const float4*>(g_part[1][r]);
#pragma unroll
    for (int s = 0; s < JSPLIT / 4; ++s) {
        float4 a = pp[s];
        float4 c = tp[s];
        rp += (a.x + a.y) + (a.z + a.w);
        rt += (c.x + c.y) + (c.z + c.w);
    }
    double dp = (double)rp, dt = (double)rt;
    double sp  = dp,      st  = dt;
    double spp = dp * dp, stt = dt * dt, spt = dp * dt;

    // warp reduction (fixed order)
#pragma unroll
    for (int o = 16; o > 0; o >>= 1) {
        sp  += __shfl_down_sync(0xffffffffu, sp,  o);
        st  += __shfl_down_sync(0xffffffffu, st,  o);
        spp += __shfl_down_sync(0xffffffffu, spp, o);
        stt += __shfl_down_sync(0xffffffffu, stt, o);
        spt += __shfl_down_sync(0xffffffffu, spt, o);
    }
    if (lane == 0) {
        red[0][w] = sp;  red[1][w] = st;
        red[2][w] = spp; red[3][w] = stt; red[4][w] = spt;
    }
    __syncthreads();

    if (tid == 0) {
        double a0 = 0, a1 = 0, a2 = 0, a3 = 0, a4 = 0;
#pragma unroll
        for (int k = 0; k < 8; ++k) {
            a0 += red[0][k]; a1 += red[1][k]; a2 += red[2][k];
            a3 += red[3][k]; a4 += red[4][k];
        }
        g_stats[blockIdx.x][0] = a0;
        g_stats[blockIdx.x][1] = a1;
        g_stats[blockIdx.x][2] = a2;
        g_stats[blockIdx.x][3] = a3;
        g_stats[blockIdx.x][4] = a4;
    }
}

// Stage 3: one warp combines the 32 block partials (fixed shfl-tree order).
__global__ void combine_kernel(float* __restrict__ out) {
    const int l = threadIdx.x;   // 0..31, one lane per stats block
    double sp  = g_stats[l][0];
    double st  = g_stats[l][1];
    double spp = g_stats[l][2];
    double stt = g_stats[l][3];
    double spt = g_stats[l][4];
#pragma unroll
    for (int o = 16; o > 0; o >>= 1) {
        sp  += __shfl_down_sync(0xffffffffu, sp,  o);
        st  += __shfl_down_sync(0xffffffffu, st,  o);
        spp += __shfl_down_sync(0xffffffffu, spp, o);
        stt += __shfl_down_sync(0xffffffffu, stt, o);
        spt += __shfl_down_sync(0xffffffffu, spt, o);
    }
    if (l == 0) {
        const double n  = (double)NN;
        const double mp = sp / n;
        const double mt = st / n;
        double num = spt - n * mp * mt;          // sum(p_c * t_c)
        double dpp = spp - n * mp * mp;          // sum(p_c^2)
        double dtt = stt - n * mt * mt;          // sum(t_c^2)
        double ic  = num / (sqrt(dpp * dtt) + 1e-8);
        out[0] = (float)(-ic);
    }
}

extern "C" void kernel_launch(void* const* d_in, const int* in_sizes, int n_in,
                              void* d_out, int out_size) {
    const float* pred = (const float*)d_in[0];
    const float* targ = (const float*)d_in[1];

    // 2 matrices * 32 row-blocks * 16 j-splits = 1024 blocks, all co-resident.
    rank_kernel<<<2 * ROWBLKS * JSPLIT, 256>>>(pred, targ);
    stats_kernel<<<SBLOCKS, SROWS>>>();
    combine_kernel<<<1, 32>>>((float*)d_out);
}

// round 11
// speedup vs baseline: 1.9684x; 1.1404x over previous
#include <cuda_runtime.h>

// ICLoss: negative soft-rank information coefficient.
//   r_i = sum_j sigmoid(x_i - x_j) + 1
// Using u = exp(x):  sigmoid(x_i - x_j) = u_i / (u_i + u_j)
//   => r_i = u_i * sum_j 1/(ui + uj) + 1
//
// Round-11 inner loop: group-of-8 polynomial trick.
//   Q(x)  = prod_{j in G} (x + u_j)   (monic, coeffs e1..e8 all positive)
//   sum_{j in G} 1/(ui + u_j) = Q'(ui) / Q(ui)
// Dual Horner evaluates Q and Q' together: 2 FFMA per pair. One MUFU.RCP per
// EIGHT pairs. Coefficients precomputed per block into SMEM (cancellation-free:
// all-positive coefficients evaluated at positive x).

#define NN 8192
#define JSPLIT 16
#define CHUNK 512            // NN / JSPLIT
#define GSIZE 8              // j's per polynomial group
#define GROUPS (CHUNK / GSIZE)  // 64 groups per chunk
#define ROWS 256             // rows per block
#define ROWBLKS 32           // NN / ROWS

#define SBLOCKS 32           // stats blocks
#define SROWS   256          // rows per stats block (NN / SBLOCKS)

// Scratch (no device allocation allowed -> __device__ globals).
__device__ float  g_part[2][NN][JSPLIT];
__device__ double g_stats[SBLOCKS][5];
__device__ unsigned int g_done = 0;   // atomicInc with limit SBLOCKS-1 self-resets

__global__ void __launch_bounds__(256) rank_kernel(const float* __restrict__ pred,
                                                   const float* __restrict__ targ) {
    __shared__ float4 sc[GROUPS][2];   // (e1..e4), (e5..e8) per group

    const int b   = blockIdx.x;
    const int js  = b & (JSPLIT - 1);        // which 512-column chunk
    const int rb  = (b >> 4) & (ROWBLKS - 1);// which 256-row block
    const int m   = b >> 9;                  // 0 = predictions, 1 = targets
    const int tid = threadIdx.x;

    const float* __restrict__ x = m ? targ : pred;

    // Setup: threads 0..63 each expand one group's polynomial coefficients.
    if (tid < GROUPS) {
        const float4* gx = reinterpret_cast<const float4*>(x + js * CHUNK + tid * GSIZE);
        float4 x0 = gx[0], x1 = gx[1];
        float u[GSIZE] = { __expf(x0.x), __expf(x0.y), __expf(x0.z), __expf(x0.w),
                           __expf(x1.x), __expf(x1.y), __expf(x1.z), __expf(x1.w) };
        // c[0..8]: monic poly coefficients, c[0]=1 leading. Multiply by (x+u_l):
        // c[k] = c[k] + u*c[k-1], k descending.
        float c[GSIZE + 1];
        c[0] = 1.0f;
#pragma unroll
        for (int k = 1; k <= GSIZE; ++k) c[k] = 0.0f;
#pragma unroll
        for (int l = 0; l < GSIZE; ++l) {
#pragma unroll
            for (int k = GSIZE; k >= 1; --k)
                c[k] = __fmaf_rn(u[l], c[k - 1], c[k]);
        }
        sc[tid][0] = make_float4(c[1], c[2], c[3], c[4]);
        sc[tid][1] = make_float4(c[5], c[6], c[7], c[8]);
    }

    const int   i  = rb * ROWS + tid;
    const float ui = __expf(x[i]);
    __syncthreads();

    // acc = sum over chunk of 1/(ui + uj) via Q'(ui)/Q(ui) per group.
    float acc = 0.0f;
#pragma unroll 8
    for (int k = 0; k < GROUPS; ++k) {
        float4 A = sc[k][0];
        float4 B = sc[k][1];
        // Dual Horner: q tracks Q, qp tracks Q'.
        float q  = ui + A.x;           // x + e1
        float qp = 1.0f;
        qp = __fmaf_rn(qp, ui, q);  q = __fmaf_rn(q, ui, A.y);   // e2
        qp = __fmaf_rn(qp, ui, q);  q = __fmaf_rn(q, ui, A.z);   // e3
        qp = __fmaf_rn(qp, ui, q);  q = __fmaf_rn(q, ui, A.w);   // e4
        qp = __fmaf_rn(qp, ui, q);  q = __fmaf_rn(q, ui, B.x);   // e5
        qp = __fmaf_rn(qp, ui, q);  q = __fmaf_rn(q, ui, B.y);   // e6
        qp = __fmaf_rn(qp, ui, q);  q = __fmaf_rn(q, ui, B.z);   // e7
        qp = __fmaf_rn(qp, ui, q);  q = __fmaf_rn(q, ui, B.w);   // e8
        float r;
        asm("rcp.approx.f32 %0, %1;" : "=f"(r) : "f"(q));
        acc = __fmaf_rn(qp, r, acc);   // += Q'(ui)/Q(ui)
    }

    g_part[m][i][js] = ui * acc;       // partial of sum_j sigmoid(x_i - x_j)
}

// Stage 2 (+fused stage 3): 32 blocks x 256 threads, one row per thread.
// Assemble ranks from the 16 j-split partials (coalesced float4 loads),
// accumulate 5 fp64 moments, block-reduce in fixed order, write per-block
// partials. The last block to finish combines the 32 partials (fixed order)
// and writes -ic. atomicInc with limit SBLOCKS-1 wraps back to 0 -> the
// counter self-resets every replay (graph-deterministic).
__global__ void __launch_bounds__(256) stats_kernel(float* __restrict__ out) {
    __shared__ double red[5][8];
    __shared__ int isLast;
    const int tid  = threadIdx.x;
    const int lane = tid & 31;
    const int w    = tid >> 5;
    const int r    = blockIdx.x * SROWS + tid;

    float rp = 1.0f, rt = 1.0f;   // +1.0 from the reference rank definition
    const float4* pp = reinterpret_cast<const float4*>(g_part[0][r]);
    const float4* tp = reinterpret_cast<const float4*>(g_part[1][r]);
#pragma unroll
    for (int s = 0; s < JSPLIT / 4; ++s) {
        float4 a = pp[s];
        float4 c = tp[s];
        rp += (a.x + a.y) + (a.z + a.w);
        rt += (c.x + c.y) + (c.z + c.w);
    }
    double dp = (double)rp, dt = (double)rt;
    double sp  = dp,      st  = dt;
    double spp = dp * dp, stt = dt * dt, spt = dp * dt;

    // warp reduction (fixed order)
#pragma unroll
    for (int o = 16; o > 0; o >>= 1) {
        sp  += __shfl_down_sync(0xffffffffu, sp,  o);
        st  += __shfl_down_sync(0xffffffffu, st,  o);
        spp += __shfl_down_sync(0xffffffffu, spp, o);
        stt += __shfl_down_sync(0xffffffffu, stt, o);
        spt += __shfl_down_sync(0xffffffffu, spt, o);
    }
    if (lane == 0) {
        red[0][w] = sp;  red[1][w] = st;
        red[2][w] = spp; red[3][w] = stt; red[4][w] = spt;
    }
    __syncthreads();

    if (tid == 0) {
        double a0 = 0, a1 = 0, a2 = 0, a3 = 0, a4 = 0;
#pragma unroll
        for (int k = 0; k < 8; ++k) {
            a0 += red[0][k]; a1 += red[1][k]; a2 += red[2][k];
            a3 += red[3][k]; a4 += red[4][k];
        }
        g_stats[blockIdx.x][0] = a0;
        g_stats[blockIdx.x][1] = a1;
        g_stats[blockIdx.x][2] = a2;
        g_stats[blockIdx.x][3] = a3;
        g_stats[blockIdx.x][4] = a4;
        __threadfence();
        isLast = (atomicInc(&g_done, SBLOCKS - 1) == SBLOCKS - 1);
    }
    __syncthreads();

    if (isLast && w == 0) {
        __threadfence();   // acquire g_stats written by all blocks
        double sp2  = g_stats[lane][0];
        double st2  = g_stats[lane][1];
        double spp2 = g_stats[lane][2];
        double stt2 = g_stats[lane][3];
        double spt2 = g_stats[lane][4];
#pragma unroll
        for (int o = 16; o > 0; o >>= 1) {
            sp2  += __shfl_down_sync(0xffffffffu, sp2,  o);
            st2  += __shfl_down_sync(0xffffffffu, st2,  o);
            spp2 += __shfl_down_sync(0xffffffffu, spp2, o);
            stt2 += __shfl_down_sync(0xffffffffu, stt2, o);
            spt2 += __shfl_down_sync(0xffffffffu, spt2, o);
        }
        if (lane == 0) {
            const double n  = (double)NN;
            const double mp = sp2 / n;
            const double mt = st2 / n;
            double num = spt2 - n * mp * mt;          // sum(p_c * t_c)
            double dpp = spp2 - n * mp * mp;          // sum(p_c^2)
            double dtt = stt2 - n * mt * mt;          // sum(t_c^2)
            double ic  = num / (sqrt(dpp * dtt) + 1e-8);
            out[0] = (float)(-ic);
        }
    }
}

extern "C" void kernel_launch(void* const* d_in, const int* in_sizes, int n_in,
                              void* d_out, int out_size) {
    const float* pred = (const float*)d_in[0];
    const float* targ = (const float*)d_in[1];

    // 2 matrices * 32 row-blocks * 16 j-splits = 1024 blocks.
    rank_kernel<<<2 * ROWBLKS * JSPLIT, 256>>>(pred, targ);
    stats_kernel<<<SBLOCKS, SROWS>>>((float*)d_out);
}

// round 12
// speedup vs baseline: 2.3074x; 1.1722x over previous
#include <cuda_runtime.h>

// ICLoss: negative soft-rank information coefficient.
//   r_i = sum_j sigmoid(x_i - x_j) + 1
// Using u = exp(x):  sigmoid(x_i - x_j) = u_i / (u_i + u_j)
//   => r_i = u_i * sum_j 1/(ui + uj) + 1
//
// Round-12 inner loop: group-of-8 polynomial trick, TWO groups at a time via
// packed fp32x2 FMA (PTX fma.rn.f32x2 -> SASS FFMA2).
//   Q(x) = prod_{j in G} (x + u_j);  sum_{j in G} 1/(ui+u_j) = Q'(ui)/Q(ui)
// Dual Horner on packed (q_A|q_B), (qp_A|qp_B) with interleaved coefficient
// pairs: 15 packed fma-pipe ops per 16 pairs (~1.2 warp-instr/pair on the
// binding fma pipe, was 2). One MUFU.RCP per 16 pairs via
//   qpA/qA + qpB/qB = (qpA*qB + qpB*qA) * rcp(qA*qB).

#define NN 8192
#define JSPLIT 16
#define CHUNK 512               // NN / JSPLIT
#define GSIZE 8                 // j's per polynomial group
#define GROUPS (CHUNK / GSIZE)  // 64 groups per chunk
#define PAIRS (GROUPS / 2)      // 32 group-pairs per chunk
#define ROWS 256                // rows per block
#define ROWBLKS 32              // NN / ROWS

#define SBLOCKS 64              // stats blocks
#define SROWS   128             // rows per stats block (NN / SBLOCKS)

// Scratch (no device allocation allowed -> __device__ globals).
__device__ float  g_part[2][NN][JSPLIT];
__device__ double g_stats[SBLOCKS][5];
__device__ unsigned int g_done = 0;   // atomicInc with limit SBLOCKS-1 self-resets

__device__ __forceinline__ unsigned long long fma2(unsigned long long a,
                                                   unsigned long long b,
                                                   unsigned long long c) {
    unsigned long long d;
    asm("fma.rn.f32x2 %0, %1, %2, %3;" : "=l"(d) : "l"(a), "l"(b), "l"(c));
    return d;
}
__device__ __forceinline__ unsigned long long add2(unsigned long long a,
                                                   unsigned long long b) {
    unsigned long long d;
    asm("add.rn.f32x2 %0, %1, %2;" : "=l"(d) : "l"(a), "l"(b));
    return d;
}

__global__ void __launch_bounds__(256) rank_kernel(const float* __restrict__ pred,
                                                   const float* __restrict__ targ) {
    // Interleaved coeff pairs: for group-pair p, float view index
    //   p*16 + j*2 + half  holds e_{j+1} of group 2p+half  (j = 0..7).
    // ulonglong2 view: sc[p*4+m].x = (eA_{2m+1}|eB_{2m+1}), .y = (eA_{2m+2}|eB_{2m+2}).
    __shared__ ulonglong2 sc[PAIRS * 4];

    const int b   = blockIdx.x;
    const int js  = b & (JSPLIT - 1);        // which 512-column chunk
    const int rb  = (b >> 4) & (ROWBLKS - 1);// which 256-row block
    const int m   = b >> 9;                  // 0 = predictions, 1 = targets
    const int tid = threadIdx.x;

    const float* __restrict__ x = m ? targ : pred;

    // Setup: threads 0..63 each expand one group's monic polynomial coeffs.
    if (tid < GROUPS) {
        const float4* gx = reinterpret_cast<const float4*>(x + js * CHUNK + tid * GSIZE);
        float4 x0 = gx[0], x1 = gx[1];
        float u[GSIZE] = { __expf(x0.x), __expf(x0.y), __expf(x0.z), __expf(x0.w),
                           __expf(x1.x), __expf(x1.y), __expf(x1.z), __expf(x1.w) };
        float c[GSIZE + 1];
        c[0] = 1.0f;
#pragma unroll
        for (int k = 1; k <= GSIZE; ++k) c[k] = 0.0f;
#pragma unroll
        for (int l = 0; l < GSIZE; ++l) {
#pragma unroll
            for (int k = GSIZE; k >= 1; --k)
                c[k] = __fmaf_rn(u[l], c[k - 1], c[k]);
        }
        float* scf = reinterpret_cast<float*>(sc);
        const int p = tid >> 1, half = tid & 1;
#pragma unroll
        for (int j = 0; j < GSIZE; ++j)
            scf[p * 16 + j * 2 + half] = c[j + 1];
    }

    const int   i  = rb * ROWS + tid;
    const float ui = __expf(x[i]);
    __syncthreads();

    unsigned long long ui2;
    {
        unsigned int uib = __float_as_uint(ui);
        asm("mov.b64 %0, {%1, %1};" : "=l"(ui2) : "r"(uib));
    }

    // acc = sum over chunk of 1/(ui + uj), two groups of 8 per iteration.
    float acc = 0.0f;
#pragma unroll 4
    for (int p = 0; p < PAIRS; ++p) {
        ulonglong2 v0 = sc[p * 4 + 0];   // e1|e2 pairs
        ulonglong2 v1 = sc[p * 4 + 1];   // e3|e4
        ulonglong2 v2 = sc[p * 4 + 2];   // e5|e6
        ulonglong2 v3 = sc[p * 4 + 3];   // e7|e8

        unsigned long long q, qp;
        q  = add2(ui2, v0.x);            // q1 = x + e1           (both groups)
        qp = add2(ui2, q);               // qp2 = x + q1
        q  = fma2(q, ui2, v0.y);         // q2
        qp = fma2(qp, ui2, q);  q = fma2(q, ui2, v1.x);   // e3
        qp = fma2(qp, ui2, q);  q = fma2(q, ui2, v1.y);   // e4
        qp = fma2(qp, ui2, q);  q = fma2(q, ui2, v2.x);   // e5
        qp = fma2(qp, ui2, q);  q = fma2(q, ui2, v2.y);   // e6
        qp = fma2(qp, ui2, q);  q = fma2(q, ui2, v3.x);   // e7
        qp = fma2(qp, ui2, q);  q = fma2(q, ui2, v3.y);   // e8

        unsigned int qa, qb, qpa, qpb;
        asm("mov.b64 {%0, %1}, %2;" : "=r"(qa),  "=r"(qb)  : "l"(q));
        asm("mov.b64 {%0, %1}, %2;" : "=r"(qpa), "=r"(qpb) : "l"(qp));
        float qA  = __uint_as_float(qa),  qB  = __uint_as_float(qb);
        float qpA = __uint_as_float(qpa), qpB = __uint_as_float(qpb);

        float den = qA * qB;
        float num = __fmaf_rn(qpA, qB, qpB * qA);
        float r;
        asm("rcp.approx.f32 %0, %1;" : "=f"(r) : "f"(den));
        acc = __fmaf_rn(num, r, acc);    // += Q'A/QA + Q'B/QB
    }

    g_part[m][i][js] = ui * acc;         // partial of sum_j sigmoid(x_i - x_j)
}

// Stage 2 (+fused stage 3): 64 blocks x 128 threads, one row per thread.
// All 8 float4 partial loads issued up-front (MLP=8) before any arithmetic.
// Fixed-order fp64 reductions; last block (atomicInc, self-resetting counter)
// combines the 64 per-block partials in fixed order and writes -ic.
__global__ void __launch_bounds__(128) stats_kernel(float* __restrict__ out) {
    __shared__ double red[5][4];
    __shared__ int isLast;
    const int tid  = threadIdx.x;
    const int lane = tid & 31;
    const int w    = tid >> 5;
    const int r    = blockIdx.x * SROWS + tid;

    const float4* pp = reinterpret_cast<const float4*>(g_part[0][r]);
    const float4* tp = reinterpret_cast<const float4*>(g_part[1][r]);
    float4 a0 = pp[0], a1 = pp[1], a2 = pp[2], a3 = pp[3];
    float4 c0 = tp[0], c1 = tp[1], c2 = tp[2], c3 = tp[3];

    float rp = 1.0f + ((a0.x + a0.y) + (a0.z + a0.w))
                    + ((a1.x + a1.y) + (a1.z + a1.w))
                    + ((a2.x + a2.y) + (a2.z + a2.w))
                    + ((a3.x + a3.y) + (a3.z + a3.w));
    float rt = 1.0f + ((c0.x + c0.y) + (c0.z + c0.w))
                    + ((c1.x + c1.y) + (c1.z + c1.w))
                    + ((c2.x + c2.y) + (c2.z + c2.w))
                    + ((c3.x + c3.y) + (c3.z + c3.w));

    double dp = (double)rp, dt = (double)rt;
    double sp  = dp,      st  = dt;
    double spp = dp * dp, stt = dt * dt, spt = dp * dt;

    // warp reduction (fixed order)
#pragma unroll
    for (int o = 16; o > 0; o >>= 1) {
        sp  += __shfl_down_sync(0xffffffffu, sp,  o);
        st  += __shfl_down_sync(0xffffffffu, st,  o);
        spp += __shfl_down_sync(0xffffffffu, spp, o);
        stt += __shfl_down_sync(0xffffffffu, stt, o);
        spt += __shfl_down_sync(0xffffffffu, spt, o);
    }
    if (lane == 0) {
        red[0][w] = sp;  red[1][w] = st;
        red[2][w] = spp; red[3][w] = stt; red[4][w] = spt;
    }
    __syncthreads();

    if (tid == 0) {
        double a = 0, bb = 0, c = 0, d = 0, e = 0;
#pragma unroll
        for (int k = 0; k < 4; ++k) {
            a += red[0][k]; bb += red[1][k]; c += red[2][k];
            d += red[3][k]; e  += red[4][k];
        }
        g_stats[blockIdx.x][0] = a;
        g_stats[blockIdx.x][1] = bb;
        g_stats[blockIdx.x][2] = c;
        g_stats[blockIdx.x][3] = d;
        g_stats[blockIdx.x][4] = e;
        __threadfence();
        isLast = (atomicInc(&g_done, SBLOCKS - 1) == SBLOCKS - 1);
    }
    __syncthreads();

    if (isLast && w == 0) {
        __threadfence();   // acquire all blocks' g_stats
        double sp2  = g_stats[lane][0] + g_stats[lane + 32][0];
        double st2  = g_stats[lane][1] + g_stats[lane + 32][1];
        double spp2 = g_stats[lane][2] + g_stats[lane + 32][2];
        double stt2 = g_stats[lane][3] + g_stats[lane + 32][3];
        double spt2 = g_stats[lane][4] + g_stats[lane + 32][4];
#pragma unroll
        for (int o = 16; o > 0; o >>= 1) {
            sp2  += __shfl_down_sync(0xffffffffu, sp2,  o);
            st2  += __shfl_down_sync(0xffffffffu, st2,  o);
            spp2 += __shfl_down_sync(0xffffffffu, spp2, o);
            stt2 += __shfl_down_sync(0xffffffffu, stt2, o);
            spt2 += __shfl_down_sync(0xffffffffu, spt2, o);
        }
        if (lane == 0) {
            const double n  = (double)NN;
            const double mp = sp2 / n;
            const double mt = st2 / n;
            double num = spt2 - n * mp * mt;          // sum(p_c * t_c)
            double dpp = spp2 - n * mp * mp;          // sum(p_c^2)
            double dtt = stt2 - n * mt * mt;          // sum(t_c^2)
            double ic  = num / (sqrt(dpp * dtt) + 1e-8);
            out[0] = (float)(-ic);
        }
    }
}

extern "C" void kernel_launch(void* const* d_in, const int* in_sizes, int n_in,
                              void* d_out, int out_size) {
    const float* pred = (const float*)d_in[0];
    const float* targ = (const float*)d_in[1];

    // 2 matrices * 32 row-blocks * 16 j-splits = 1024 blocks.
    rank_kernel<<<2 * ROWBLKS * JSPLIT, 256>>>(pred, targ);
    stats_kernel<<<SBLOCKS, SROWS>>>((float*)d_out);
}